// round 6
// baseline (speedup 1.0000x reference)
#include <cuda_runtime.h>
#include <cuda_fp16.h>
#include <cstdint>

#define DNODES 128
#define HID    512
#define NSAMP  2048
#define TM     128
#define THREADS 512
#define NTILES 40           // 8 (L0: K=128 x 2 chunks) + 32 (L1: K=512 x 2 chunks), KT=32

// smem byte offsets
#define APH_B   0                     // h1 packed: 32 ksteps x 8 mf x 512B = 128KB
#define APX_B   98304                 // x packed: 8 ksteps x 8 mf x 512B = 32KB (aliases APH ksteps 24..31)
#define BB_B    131072                // 3 x 16KB B staging ring
#define BTILE_B 16384
#define W2_B    180224                // 512 f32
#define OUTS_B  182272                // 128 f32
#define SMEMB   182784

// packed fp16 weights, fragment-major: [d][c(2)][kt][s(2)][q(16)][lane(32)] x 16B
__device__ __half g_Wp0[(size_t)DNODES * 2 * 4  * 2 * 16 * 32 * 8];
__device__ __half g_Wp1[(size_t)DNODES * 2 * 16 * 2 * 16 * 32 * 8];

__device__ __forceinline__ float leaky(float x) { return x > 0.0f ? x : 0.01f * x; }

__device__ __forceinline__ void mma_f16(float c[4], uint32_t a0, uint32_t a1,
                                        uint32_t a2, uint32_t a3,
                                        uint32_t b0, uint32_t b1) {
    asm volatile(
        "mma.sync.aligned.m16n8k16.row.col.f32.f16.f16.f32 "
        "{%0,%1,%2,%3},{%4,%5,%6,%7},{%8,%9},{%0,%1,%2,%3};"
        : "+f"(c[0]), "+f"(c[1]), "+f"(c[2]), "+f"(c[3])
        : "r"(a0), "r"(a1), "r"(a2), "r"(a3), "r"(b0), "r"(b1));
}
__device__ __forceinline__ uint32_t smem_u32(const void* p) {
    uint32_t a;
    asm("{ .reg .u64 t; cvta.to.shared.u64 t, %1; cvt.u32.u64 %0, t; }" : "=r"(a) : "l"(p));
    return a;
}
#define CP_ASYNC16(sa, gp) \
    asm volatile("cp.async.cg.shared.global [%0], [%1], 16;" :: "r"((uint32_t)(sa)), "l"(gp) : "memory")
#define CP_COMMIT() asm volatile("cp.async.commit_group;" ::: "memory")
#define CP_WAIT1()  asm volatile("cp.async.wait_group 1;" ::: "memory")
#define CP_WAIT0()  asm volatile("cp.async.wait_group 0;" ::: "memory")

__device__ __forceinline__ uint32_t pack_h2f(float lo, float hi) {
    __half2 h = __halves2half2(__float2half_rn(lo), __float2half_rn(hi));
    return *reinterpret_cast<uint32_t*>(&h);
}

// ---------- prepass v2: coalesced read -> smem transpose -> fragment-major write ----------
// out uint4 index: (((d*2 + c)*KT32 + kt)*2 + s)*512 + q*32 + lane
// frag: r.x=(colb,k0/k0+1) r.y=(colb,k0+8/9) r.z=(colb+8,k0/k0+1) r.w=(colb+8,k0+8/9)
template <int KT32>
__global__ void pack_w2(const float* __restrict__ W, __half* __restrict__ Wp) {
    __shared__ __half T[512 * 34];
    int kt = blockIdx.x, d = blockIdx.y;
    const float* src = W + ((size_t)d * KT32 * 32 + kt * 32) * HID;

    for (int fid = threadIdx.x; fid < 4096; fid += 256) {
        int k = fid >> 7, c4 = fid & 127;
        float4 v = *reinterpret_cast<const float4*>(src + (size_t)k * HID + c4 * 4);
        T[(c4 * 4 + 0) * 34 + k] = __float2half_rn(v.x);
        T[(c4 * 4 + 1) * 34 + k] = __float2half_rn(v.y);
        T[(c4 * 4 + 2) * 34 + k] = __float2half_rn(v.z);
        T[(c4 * 4 + 3) * 34 + k] = __float2half_rn(v.w);
    }
    __syncthreads();

    for (int oi = threadIdx.x; oi < 2048; oi += 256) {
        int lane = oi & 31, q = (oi >> 5) & 15, s = (oi >> 9) & 1, c = oi >> 10;
        int g = lane >> 2, t4 = lane & 3;
        int colb = c * 256 + (q >> 2) * 64 + (q & 3) * 16 + g;
        int k0 = s * 16 + 2 * t4;
        uint4 u;
        u.x = *reinterpret_cast<const uint32_t*>(T + colb * 34 + k0);
        u.y = *reinterpret_cast<const uint32_t*>(T + colb * 34 + k0 + 8);
        u.z = *reinterpret_cast<const uint32_t*>(T + (colb + 8) * 34 + k0);
        u.w = *reinterpret_cast<const uint32_t*>(T + (colb + 8) * 34 + k0 + 8);
        size_t oidx = ((((size_t)d * 2 + c) * KT32 + kt) * 2 + s) * 512 + q * 32 + lane;
        reinterpret_cast<uint4*>(Wp)[oidx] = u;
    }
}

// ---------- main fused kernel ----------
extern __shared__ char smc[];

__global__ void __launch_bounds__(THREADS, 1)
grandag_f16_kernel(const float* __restrict__ x,
                   const float* __restrict__ W2,
                   float* __restrict__ out) {
    const int tid = threadIdx.x;
    const int warp = tid >> 5;
    const int lane = tid & 31;
    const int wm = warp & 3;      // 4 M-warps (32 rows each)
    const int wn = warp >> 2;     // 4 N-warps (64 cols each)
    const int g = lane >> 2;
    const int t4 = lane & 3;
    const int d = blockIdx.y;
    const int n0 = blockIdx.x * TM;
    const uint32_t sb = smem_u32(smc);
    float* smf = reinterpret_cast<float*>(smc);

    if (tid < TM) smf[OUTS_B / 4 + tid] = 0.0f;
    if (tid < HID) smf[W2_B / 4 + tid] = W2[(size_t)d * HID + tid];

    // pack masked x -> APX fragment-major: [kstep(8)][mf(8)][512B]
    {
        const float* xb = x + (size_t)n0 * DNODES;
        int K = warp & 7;
        int mh = warp >> 3;
        int k0 = K * 16 + 2 * t4;
#pragma unroll
        for (int i = 0; i < 4; i++) {
            int mf = mh * 4 + i;
            int r0 = mf * 16 + g, r1 = r0 + 8;
            float v[8];
            v[0] = xb[(size_t)r0 * DNODES + k0];     v[1] = xb[(size_t)r0 * DNODES + k0 + 1];
            v[2] = xb[(size_t)r1 * DNODES + k0];     v[3] = xb[(size_t)r1 * DNODES + k0 + 1];
            v[4] = xb[(size_t)r0 * DNODES + k0 + 8]; v[5] = xb[(size_t)r0 * DNODES + k0 + 9];
            v[6] = xb[(size_t)r1 * DNODES + k0 + 8]; v[7] = xb[(size_t)r1 * DNODES + k0 + 9];
            if (k0 == d)     { v[0] = 0.f; v[2] = 0.f; }
            if (k0 + 1 == d) { v[1] = 0.f; v[3] = 0.f; }
            if (k0 + 8 == d) { v[4] = 0.f; v[6] = 0.f; }
            if (k0 + 9 == d) { v[5] = 0.f; v[7] = 0.f; }
            uint4 u = make_uint4(pack_h2f(v[0], v[1]), pack_h2f(v[2], v[3]),
                                 pack_h2f(v[4], v[5]), pack_h2f(v[6], v[7]));
            *reinterpret_cast<uint4*>(smc + APX_B + (K * 8 + mf) * 512 + lane * 16) = u;
        }
    }

    auto tsrc = [&](int t) -> const __half* {
        if (t < 8) {
            int c = t >> 2, kt = t & 3;
            return g_Wp0 + ((((size_t)d * 2 + c) * 4 + kt) * 1024) * 8;
        }
        int u = t - 8;
        int c = u >> 4, kt = u & 15;
        return g_Wp1 + ((((size_t)d * 2 + c) * 16 + kt) * 1024) * 8;
    };
    auto stage = [&](int t) {
        const __half* gsrc = tsrc(t);
        uint32_t dstb = sb + BB_B + (uint32_t)(t % 3) * BTILE_B;
#pragma unroll
        for (int q = 0; q < 2; q++) {
            int fid = tid + q * THREADS;      // 0..1023 x 16B
            CP_ASYNC16(dstb + fid * 16, gsrc + (size_t)fid * 8);
        }
    };

    stage(0); CP_COMMIT();
    stage(1); CP_COMMIT();

    float acc[2][8][4];
    float pr[4] = {0.f, 0.f, 0.f, 0.f};

#pragma unroll 1
    for (int t = 0; t < NTILES; t++) {
        if (t < NTILES - 1) CP_WAIT1(); else CP_WAIT0();
        __syncthreads();   // tile t visible; tile t-1 fully consumed everywhere
        if (t + 2 < NTILES) { stage(t + 2); CP_COMMIT(); }

        bool first = (t < 8) ? ((t & 3) == 0) : (((t - 8) & 15) == 0);
        if (first) {
#pragma unroll
            for (int mf = 0; mf < 2; mf++)
#pragma unroll
                for (int s = 0; s < 8; s++)
#pragma unroll
                    for (int j = 0; j < 4; j++) acc[mf][s][j] = 0.f;
        }

        const int abase = (t < 8) ? (APX_B + (t & 3) * 2 * 4096)
                                  : (APH_B + ((t - 8) & 15) * 2 * 4096);
        const char* bb = smc + BB_B + (t % 3) * BTILE_B;

#pragma unroll
        for (int ks = 0; ks < 2; ks++) {
            uint4 a[2];
#pragma unroll
            for (int mf = 0; mf < 2; mf++)
                a[mf] = *reinterpret_cast<const uint4*>(
                    smc + abase + ks * 4096 + (wm * 2 + mf) * 512 + lane * 16);
#pragma unroll
            for (int p = 0; p < 4; p++) {
                uint4 b = *reinterpret_cast<const uint4*>(
                    bb + (((ks * 16) + wn * 4 + p) * 32 + lane) * 16);
                mma_f16(acc[0][2 * p],     a[0].x, a[0].y, a[0].z, a[0].w, b.x, b.y);
                mma_f16(acc[0][2 * p + 1], a[0].x, a[0].y, a[0].z, a[0].w, b.z, b.w);
                mma_f16(acc[1][2 * p],     a[1].x, a[1].y, a[1].z, a[1].w, b.x, b.y);
                mma_f16(acc[1][2 * p + 1], a[1].x, a[1].y, a[1].z, a[1].w, b.z, b.w);
            }
        }

        // L0 chunk epilogue: leaky -> fp16 -> APH fragment-major (conflict-free STS.128)
        if (t == 3 || t == 7) {
            if (t == 7) __syncthreads();   // all x reads done before overwriting aliased APX
            int c = t >> 2;
#pragma unroll
            for (int mf = 0; mf < 2; mf++) {
#pragma unroll
                for (int p = 0; p < 4; p++) {
                    int K = c * 16 + wn * 4 + p;
                    int se = 2 * p, so = 2 * p + 1;
                    uint4 u = make_uint4(
                        pack_h2f(leaky(acc[mf][se][0]), leaky(acc[mf][se][1])),
                        pack_h2f(leaky(acc[mf][se][2]), leaky(acc[mf][se][3])),
                        pack_h2f(leaky(acc[mf][so][0]), leaky(acc[mf][so][1])),
                        pack_h2f(leaky(acc[mf][so][2]), leaky(acc[mf][so][3])));
                    *reinterpret_cast<uint4*>(
                        smc + APH_B + (K * 8 + wm * 2 + mf) * 512 + lane * 16) = u;
                }
            }
        }
        // L1 chunk epilogue: fused layer-2 dot (fp32)
        if (t == 23 || t == 39) {
            int c = (t - 8) >> 4;
#pragma unroll
            for (int mf = 0; mf < 2; mf++)
#pragma unroll
                for (int s = 0; s < 8; s++) {
                    int n = c * 256 + wn * 64 + 8 * s + 2 * t4;
                    float w2a = smf[W2_B / 4 + n], w2b = smf[W2_B / 4 + n + 1];
                    pr[mf * 2 + 0] += leaky(acc[mf][s][0]) * w2a + leaky(acc[mf][s][1]) * w2b;
                    pr[mf * 2 + 1] += leaky(acc[mf][s][2]) * w2a + leaky(acc[mf][s][3]) * w2b;
                }
        }
    }

#pragma unroll
    for (int j = 0; j < 4; j++) {
        pr[j] += __shfl_xor_sync(0xffffffffu, pr[j], 1);
        pr[j] += __shfl_xor_sync(0xffffffffu, pr[j], 2);
    }
    if (t4 == 0) {
#pragma unroll
        for (int mf = 0; mf < 2; mf++) {
            int R = wm * 32 + mf * 16;
            atomicAdd(&smf[OUTS_B / 4 + R + g], pr[mf * 2 + 0]);
            atomicAdd(&smf[OUTS_B / 4 + R + g + 8], pr[mf * 2 + 1]);
        }
    }
    __syncthreads();
    if (tid < TM)
        out[(size_t)(n0 + tid) * DNODES + d] = smf[OUTS_B / 4 + tid];
}

extern "C" void kernel_launch(void* const* d_in, const int* in_sizes, int n_in,
                              void* d_out, int out_size) {
    (void)in_sizes; (void)n_in; (void)out_size;
    const float* x  = (const float*)d_in[0];
    const float* W0 = (const float*)d_in[1];
    const float* W1 = (const float*)d_in[2];
    const float* W2 = (const float*)d_in[3];
    float* out = (float*)d_out;

    __half* wp0; cudaGetSymbolAddress((void**)&wp0, g_Wp0);
    __half* wp1; cudaGetSymbolAddress((void**)&wp1, g_Wp1);

    pack_w2<4><<<dim3(4, DNODES), 256>>>(W0, wp0);
    pack_w2<16><<<dim3(16, DNODES), 256>>>(W1, wp1);

    cudaFuncSetAttribute(grandag_f16_kernel,
                         cudaFuncAttributeMaxDynamicSharedMemorySize, SMEMB);
    dim3 grid(NSAMP / TM, DNODES);   // x fastest: same-d blocks co-resident (L2 weight reuse)
    grandag_f16_kernel<<<grid, THREADS, SMEMB>>>(x, W2, out);
}

// round 7
// speedup vs baseline: 1.2512x; 1.2512x over previous
#include <cuda_runtime.h>
#include <cuda_fp16.h>
#include <cstdint>

#define DNODES 128
#define HID    512
#define NSAMP  2048
#define TM     64
#define THREADS 128
#define NTILES 40           // 8 (L0: K=128 x 2 chunks) + 32 (L1: K=512 x 2 chunks), KT=32

// smem byte offsets (identical to round-5 footprint: 2 blocks/SM)
#define APH_B   0                     // h1 packed: 32 ksteps x 4 mf x 512B = 64KB
#define APX_B   49152                 // x packed: 8 ksteps x 4 mf x 512B = 16KB (aliases APH ksteps 24..31)
#define BB_B    65536                 // 2 x 16KB B staging
#define BTILE_B 16384
#define W2_B    98304                 // 512 f32
#define OUTS_B  100352                // 64 f32
#define SMEMB   100608

// packed fp16 weights, fragment-major: [d][c(2)][kt][s(2)][q(16)][lane(32)] x 16B
__device__ __half g_Wp0[(size_t)DNODES * 2 * 4  * 2 * 16 * 32 * 8];
__device__ __half g_Wp1[(size_t)DNODES * 2 * 16 * 2 * 16 * 32 * 8];

__device__ __forceinline__ float leaky(float x) { return x > 0.0f ? x : 0.01f * x; }

__device__ __forceinline__ void mma_f16(float c[4], uint32_t a0, uint32_t a1,
                                        uint32_t a2, uint32_t a3,
                                        uint32_t b0, uint32_t b1) {
    asm volatile(
        "mma.sync.aligned.m16n8k16.row.col.f32.f16.f16.f32 "
        "{%0,%1,%2,%3},{%4,%5,%6,%7},{%8,%9},{%0,%1,%2,%3};"
        : "+f"(c[0]), "+f"(c[1]), "+f"(c[2]), "+f"(c[3])
        : "r"(a0), "r"(a1), "r"(a2), "r"(a3), "r"(b0), "r"(b1));
}
__device__ __forceinline__ uint32_t smem_u32(const void* p) {
    uint32_t a;
    asm("{ .reg .u64 t; cvta.to.shared.u64 t, %1; cvt.u32.u64 %0, t; }" : "=r"(a) : "l"(p));
    return a;
}
#define CP_ASYNC16(sa, gp) \
    asm volatile("cp.async.cg.shared.global [%0], [%1], 16;" :: "r"((uint32_t)(sa)), "l"(gp) : "memory")
#define CP_COMMIT() asm volatile("cp.async.commit_group;" ::: "memory")
#define CP_WAIT0()  asm volatile("cp.async.wait_group 0;" ::: "memory")

__device__ __forceinline__ uint32_t pack_h2(float lo, float hi) {
    __half2 h = __halves2half2(__float2half_rn(lo), __float2half_rn(hi));
    return *reinterpret_cast<uint32_t*>(&h);
}

// ---------- prepass (round-4 version, measured fastest): fragment-major fp16 pack ----------
template <int KTOT, int LOGKT>
__global__ void pack_w(const float* __restrict__ W, __half* __restrict__ Wp) {
    size_t idx = (size_t)blockIdx.x * 256 + threadIdx.x;
    size_t total = (size_t)DNODES * 2 * (KTOT / 32) * 2 * 16 * 32;
    if (idx >= total) return;
    int lane = (int)(idx & 31);
    int q    = (int)((idx >> 5) & 15);
    int s    = (int)((idx >> 9) & 1);
    int kt   = (int)((idx >> 10) & ((KTOT / 32) - 1));
    int c    = (int)((idx >> (10 + LOGKT)) & 1);
    int d    = (int)(idx >> (11 + LOGKT));
    int g = lane >> 2, t4 = lane & 3;
    int colb = c * 256 + (q >> 2) * 64 + (q & 3) * 16 + g;
    int kb = kt * 32 + s * 16 + 2 * t4;
    const float* src = W + (size_t)d * KTOT * HID;
    uint32_t r[4];
#pragma unroll
    for (int f = 0; f < 2; f++)
#pragma unroll
        for (int hb = 0; hb < 2; hb++) {
            int k = kb + hb * 8;
            int col = colb + f * 8;
            r[f * 2 + hb] = pack_h2(src[(size_t)k * HID + col],
                                    src[(size_t)(k + 1) * HID + col]);
        }
    reinterpret_cast<uint4*>(Wp)[idx] = make_uint4(r[0], r[1], r[2], r[3]);
}

// ---------- main fused kernel: 4 warps, 64x64 warp tile ----------
extern __shared__ char smc[];

__global__ void __launch_bounds__(THREADS, 2)
grandag_f16_kernel(const float* __restrict__ x,
                   const float* __restrict__ W2,
                   float* __restrict__ out) {
    const int tid = threadIdx.x;
    const int wn = tid >> 5;      // 4 N-warps (64 cols each), each owns all 64 rows
    const int lane = tid & 31;
    const int g = lane >> 2;
    const int t4 = lane & 3;
    const int d = blockIdx.y;
    const int n0 = blockIdx.x * TM;
    const uint32_t sb = smem_u32(smc);
    float* smf = reinterpret_cast<float*>(smc);

    if (tid < TM) smf[OUTS_B / 4 + tid] = 0.0f;
    for (int i = tid; i < HID; i += THREADS)
        smf[W2_B / 4 + i] = W2[(size_t)d * HID + i];

    // pack masked x -> APX fragment-major: [kstep(8)][mf(4)][512B]
    {
        const float* xb = x + (size_t)n0 * DNODES;
#pragma unroll
        for (int kk = 0; kk < 2; kk++) {
            int K = wn + kk * 4;
            int k0 = K * 16 + 2 * t4;
#pragma unroll
            for (int mf = 0; mf < 4; mf++) {
                int r0 = mf * 16 + g, r1 = r0 + 8;
                float v[8];
                v[0] = xb[(size_t)r0 * DNODES + k0];     v[1] = xb[(size_t)r0 * DNODES + k0 + 1];
                v[2] = xb[(size_t)r1 * DNODES + k0];     v[3] = xb[(size_t)r1 * DNODES + k0 + 1];
                v[4] = xb[(size_t)r0 * DNODES + k0 + 8]; v[5] = xb[(size_t)r0 * DNODES + k0 + 9];
                v[6] = xb[(size_t)r1 * DNODES + k0 + 8]; v[7] = xb[(size_t)r1 * DNODES + k0 + 9];
                if (k0 == d)     { v[0] = 0.f; v[2] = 0.f; }
                if (k0 + 1 == d) { v[1] = 0.f; v[3] = 0.f; }
                if (k0 + 8 == d) { v[4] = 0.f; v[6] = 0.f; }
                if (k0 + 9 == d) { v[5] = 0.f; v[7] = 0.f; }
                uint4 u = make_uint4(pack_h2(v[0], v[1]), pack_h2(v[2], v[3]),
                                     pack_h2(v[4], v[5]), pack_h2(v[6], v[7]));
                *reinterpret_cast<uint4*>(smc + APX_B + (K * 4 + mf) * 512 + lane * 16) = u;
            }
        }
    }

    auto tsrc = [&](int t) -> const __half* {
        if (t < 8) {
            int c = t >> 2, kt = t & 3;
            return g_Wp0 + ((((size_t)d * 2 + c) * 4 + kt) * 1024) * 8;
        }
        int u = t - 8;
        int c = u >> 4, kt = u & 15;
        return g_Wp1 + ((((size_t)d * 2 + c) * 16 + kt) * 1024) * 8;
    };
    auto stage = [&](int t) {
        const __half* gsrc = tsrc(t);
        uint32_t dstb = sb + BB_B + (uint32_t)(t & 1) * BTILE_B;
#pragma unroll
        for (int q = 0; q < 8; q++) {
            int fid = tid + q * THREADS;      // 0..1023 x 16B
            CP_ASYNC16(dstb + fid * 16, gsrc + (size_t)fid * 8);
        }
    };

    stage(0);
    CP_COMMIT();

    float acc[4][8][4];                 // 64 rows (4 mf) x 64 cols (8 n8)
    float pr[8] = {0.f,0.f,0.f,0.f,0.f,0.f,0.f,0.f};

#pragma unroll 1
    for (int t = 0; t < NTILES; t++) {
        CP_WAIT0();
        __syncthreads();   // tile t visible; tile t-1 fully consumed everywhere
        if (t + 1 < NTILES) { stage(t + 1); CP_COMMIT(); }

        bool first = (t < 8) ? ((t & 3) == 0) : (((t - 8) & 15) == 0);
        if (first) {
#pragma unroll
            for (int mf = 0; mf < 4; mf++)
#pragma unroll
                for (int s = 0; s < 8; s++)
#pragma unroll
                    for (int j = 0; j < 4; j++) acc[mf][s][j] = 0.f;
        }

        const int abase = (t < 8) ? (APX_B + (t & 3) * 4096)
                                  : (APH_B + ((t - 8) & 15) * 4096);
        const char* bb = smc + BB_B + (t & 1) * BTILE_B;

#pragma unroll
        for (int ks = 0; ks < 2; ks++) {
            uint4 a[4];
#pragma unroll
            for (int mf = 0; mf < 4; mf++)
                a[mf] = *reinterpret_cast<const uint4*>(
                    smc + abase + ks * 2048 + mf * 512 + lane * 16);
#pragma unroll
            for (int p = 0; p < 4; p++) {
                uint4 b = *reinterpret_cast<const uint4*>(
                    bb + (((ks * 16) + wn * 4 + p) * 32 + lane) * 16);
#pragma unroll
                for (int mf = 0; mf < 4; mf++) {
                    mma_f16(acc[mf][2 * p],     a[mf].x, a[mf].y, a[mf].z, a[mf].w, b.x, b.y);
                    mma_f16(acc[mf][2 * p + 1], a[mf].x, a[mf].y, a[mf].z, a[mf].w, b.z, b.w);
                }
            }
        }

        // L0 chunk epilogue: leaky -> fp16 -> APH fragment-major (conflict-free STS.128)
        if (t == 3 || t == 7) {
            if (t == 7) __syncthreads();   // all x reads done before overwriting aliased APX
            int c = t >> 2;
#pragma unroll
            for (int mf = 0; mf < 4; mf++) {
#pragma unroll
                for (int p = 0; p < 4; p++) {
                    int K = c * 16 + wn * 4 + p;
                    int se = 2 * p, so = 2 * p + 1;
                    uint4 u = make_uint4(
                        pack_h2(leaky(acc[mf][se][0]), leaky(acc[mf][se][1])),
                        pack_h2(leaky(acc[mf][se][2]), leaky(acc[mf][se][3])),
                        pack_h2(leaky(acc[mf][so][0]), leaky(acc[mf][so][1])),
                        pack_h2(leaky(acc[mf][so][2]), leaky(acc[mf][so][3])));
                    *reinterpret_cast<uint4*>(
                        smc + APH_B + (K * 4 + mf) * 512 + lane * 16) = u;
                }
            }
        }
        // L1 chunk epilogue: fused layer-2 dot (fp32)
        if (t == 23 || t == 39) {
            int c = (t - 8) >> 4;
#pragma unroll
            for (int mf = 0; mf < 4; mf++)
#pragma unroll
                for (int s = 0; s < 8; s++) {
                    int n = c * 256 + wn * 64 + 8 * s + 2 * t4;
                    float w2a = smf[W2_B / 4 + n], w2b = smf[W2_B / 4 + n + 1];
                    pr[mf * 2 + 0] += leaky(acc[mf][s][0]) * w2a + leaky(acc[mf][s][1]) * w2b;
                    pr[mf * 2 + 1] += leaky(acc[mf][s][2]) * w2a + leaky(acc[mf][s][3]) * w2b;
                }
        }
    }

#pragma unroll
    for (int j = 0; j < 8; j++) {
        pr[j] += __shfl_xor_sync(0xffffffffu, pr[j], 1);
        pr[j] += __shfl_xor_sync(0xffffffffu, pr[j], 2);
    }
    if (t4 == 0) {
#pragma unroll
        for (int mf = 0; mf < 4; mf++) {
            int R = mf * 16;
            atomicAdd(&smf[OUTS_B / 4 + R + g], pr[mf * 2 + 0]);
            atomicAdd(&smf[OUTS_B / 4 + R + g + 8], pr[mf * 2 + 1]);
        }
    }
    __syncthreads();
    if (tid < TM)
        out[(size_t)(n0 + tid) * DNODES + d] = smf[OUTS_B / 4 + tid];
}

extern "C" void kernel_launch(void* const* d_in, const int* in_sizes, int n_in,
                              void* d_out, int out_size) {
    (void)in_sizes; (void)n_in; (void)out_size;
    const float* x  = (const float*)d_in[0];
    const float* W0 = (const float*)d_in[1];
    const float* W1 = (const float*)d_in[2];
    const float* W2 = (const float*)d_in[3];
    float* out = (float*)d_out;

    __half* wp0; cudaGetSymbolAddress((void**)&wp0, g_Wp0);
    __half* wp1; cudaGetSymbolAddress((void**)&wp1, g_Wp1);

    {
        size_t t0 = (size_t)DNODES * 2 * 4 * 2 * 16 * 32;    // uint4 count L0
        size_t t1 = (size_t)DNODES * 2 * 16 * 2 * 16 * 32;   // uint4 count L1
        pack_w<DNODES, 2><<<(unsigned)((t0 + 255) / 256), 256>>>(W0, wp0);
        pack_w<HID, 4><<<(unsigned)((t1 + 255) / 256), 256>>>(W1, wp1);
    }

    cudaFuncSetAttribute(grandag_f16_kernel,
                         cudaFuncAttributeMaxDynamicSharedMemorySize, SMEMB);
    dim3 grid(NSAMP / TM, DNODES);   // x fastest: same-d blocks co-resident (L2 weight reuse)
    grandag_f16_kernel<<<grid, THREADS, SMEMB>>>(x, W2, out);
}

// round 8
// speedup vs baseline: 1.2634x; 1.0097x over previous
#include <cuda_runtime.h>
#include <cuda_fp16.h>
#include <cstdint>

#define DNODES 128
#define HID    512
#define NSAMP  2048
#define TM     64
#define THREADS 128
#define NTILES 40           // 8 (L0: K=128 x 2 chunks) + 32 (L1: K=512 x 2 chunks), KT=32

// smem byte offsets (no B staging anymore)
#define APH_B   0                     // h1 packed: 32 ksteps x 4 mf x 512B = 64KB
#define APX_B   49152                 // x packed: 8 ksteps x 4 mf x 512B (aliases APH ksteps 24..31)
#define W2_B    65536                 // 512 f32
#define OUTS_B  67584                 // 64 f32
#define SMEMB   67840

// packed fp16 weights, fragment-major: [d][c(2)][kt][s(2)][q(16)][lane(32)] x 16B
__device__ __half g_Wp0[(size_t)DNODES * 2 * 4  * 2 * 16 * 32 * 8];
__device__ __half g_Wp1[(size_t)DNODES * 2 * 16 * 2 * 16 * 32 * 8];

__device__ __forceinline__ float leaky(float x) { return x > 0.0f ? x : 0.01f * x; }

__device__ __forceinline__ void mma_f16(float c[4], uint32_t a0, uint32_t a1,
                                        uint32_t a2, uint32_t a3,
                                        uint32_t b0, uint32_t b1) {
    asm volatile(
        "mma.sync.aligned.m16n8k16.row.col.f32.f16.f16.f32 "
        "{%0,%1,%2,%3},{%4,%5,%6,%7},{%8,%9},{%0,%1,%2,%3};"
        : "+f"(c[0]), "+f"(c[1]), "+f"(c[2]), "+f"(c[3])
        : "r"(a0), "r"(a1), "r"(a2), "r"(a3), "r"(b0), "r"(b1));
}

__device__ __forceinline__ uint32_t pack_h2(float lo, float hi) {
    __half2 h = __halves2half2(__float2half_rn(lo), __float2half_rn(hi));
    return *reinterpret_cast<uint32_t*>(&h);
}

// ---------- prepass (measured fastest variant): fragment-major fp16 pack ----------
template <int KTOT, int LOGKT>
__global__ void pack_w(const float* __restrict__ W, __half* __restrict__ Wp) {
    size_t idx = (size_t)blockIdx.x * 256 + threadIdx.x;
    size_t total = (size_t)DNODES * 2 * (KTOT / 32) * 2 * 16 * 32;
    if (idx >= total) return;
    int lane = (int)(idx & 31);
    int q    = (int)((idx >> 5) & 15);
    int s    = (int)((idx >> 9) & 1);
    int kt   = (int)((idx >> 10) & ((KTOT / 32) - 1));
    int c    = (int)((idx >> (10 + LOGKT)) & 1);
    int d    = (int)(idx >> (11 + LOGKT));
    int g = lane >> 2, t4 = lane & 3;
    int colb = c * 256 + (q >> 2) * 64 + (q & 3) * 16 + g;
    int kb = kt * 32 + s * 16 + 2 * t4;
    const float* src = W + (size_t)d * KTOT * HID;
    uint32_t r[4];
#pragma unroll
    for (int f = 0; f < 2; f++)
#pragma unroll
        for (int hb = 0; hb < 2; hb++) {
            int k = kb + hb * 8;
            int col = colb + f * 8;
            r[f * 2 + hb] = pack_h2(src[(size_t)k * HID + col],
                                    src[(size_t)(k + 1) * HID + col]);
        }
    reinterpret_cast<uint4*>(Wp)[idx] = make_uint4(r[0], r[1], r[2], r[3]);
}

// ---------- main fused kernel: 4 warps, 64x64 warp tile, register-prefetched B ----------
extern __shared__ char smc[];

__global__ void __launch_bounds__(THREADS, 2)
grandag_f16_kernel(const float* __restrict__ x,
                   const float* __restrict__ W2,
                   float* __restrict__ out) {
    const int tid = threadIdx.x;
    const int wn = tid >> 5;      // 4 N-warps (64 cols each), each owns all 64 rows
    const int lane = tid & 31;
    const int g = lane >> 2;
    const int t4 = lane & 3;
    const int d = blockIdx.y;
    const int n0 = blockIdx.x * TM;
    float* smf = reinterpret_cast<float*>(smc);

    if (tid < TM) smf[OUTS_B / 4 + tid] = 0.0f;
    for (int i = tid; i < HID; i += THREADS)
        smf[W2_B / 4 + i] = W2[(size_t)d * HID + i];

    // pack masked x -> APX fragment-major: [kstep(8)][mf(4)][512B]
    {
        const float* xb = x + (size_t)n0 * DNODES;
#pragma unroll
        for (int kk = 0; kk < 2; kk++) {
            int K = wn + kk * 4;
            int k0 = K * 16 + 2 * t4;
#pragma unroll
            for (int mf = 0; mf < 4; mf++) {
                int r0 = mf * 16 + g, r1 = r0 + 8;
                float v[8];
                v[0] = xb[(size_t)r0 * DNODES + k0];     v[1] = xb[(size_t)r0 * DNODES + k0 + 1];
                v[2] = xb[(size_t)r1 * DNODES + k0];     v[3] = xb[(size_t)r1 * DNODES + k0 + 1];
                v[4] = xb[(size_t)r0 * DNODES + k0 + 8]; v[5] = xb[(size_t)r0 * DNODES + k0 + 9];
                v[6] = xb[(size_t)r1 * DNODES + k0 + 8]; v[7] = xb[(size_t)r1 * DNODES + k0 + 9];
                if (k0 == d)     { v[0] = 0.f; v[2] = 0.f; }
                if (k0 + 1 == d) { v[1] = 0.f; v[3] = 0.f; }
                if (k0 + 8 == d) { v[4] = 0.f; v[6] = 0.f; }
                if (k0 + 9 == d) { v[5] = 0.f; v[7] = 0.f; }
                uint4 u = make_uint4(pack_h2(v[0], v[1]), pack_h2(v[2], v[3]),
                                     pack_h2(v[4], v[5]), pack_h2(v[6], v[7]));
                *reinterpret_cast<uint4*>(smc + APX_B + (K * 4 + mf) * 512 + lane * 16) = u;
            }
        }
    }
    __syncthreads();   // x pack + w2 + outs visible to all warps

    // B fragment base (uint4 granularity) for tile t, this warp
    auto bbase = [&](int t) -> const uint4* {
        const __half* gsrc;
        if (t < 8) {
            int c = t >> 2, kt = t & 3;
            gsrc = g_Wp0 + ((((size_t)d * 2 + c) * 4 + kt) * 1024) * 8;
        } else {
            int u = t - 8;
            int c = u >> 4, kt = u & 15;
            gsrc = g_Wp1 + ((((size_t)d * 2 + c) * 16 + kt) * 1024) * 8;
        }
        return reinterpret_cast<const uint4*>(gsrc) + (wn * 4) * 32 + lane;
    };

    uint4 bfrag[8];   // [ks*4+p], prefetched one tile (or half-tile) ahead
    {
        const uint4* b0 = bbase(0);
#pragma unroll
        for (int i = 0; i < 8; i++)
            bfrag[i] = b0[((i >> 2) * 16 + (i & 3)) * 32];
    }

    float acc[4][8][4];                 // 64 rows (4 mf) x 64 cols (8 n8)
    float pr[8] = {0.f,0.f,0.f,0.f,0.f,0.f,0.f,0.f};

#pragma unroll 1
    for (int t = 0; t < NTILES; t++) {
        bool first = (t < 8) ? ((t & 3) == 0) : (((t - 8) & 15) == 0);
        if (first) {
#pragma unroll
            for (int mf = 0; mf < 4; mf++)
#pragma unroll
                for (int s = 0; s < 8; s++)
#pragma unroll
                    for (int j = 0; j < 4; j++) acc[mf][s][j] = 0.f;
        }

        const int abase = (t < 8) ? (APX_B + (t & 3) * 4096)
                                  : (APH_B + ((t - 8) & 15) * 4096);
        const uint4* bnext = (t + 1 < NTILES) ? bbase(t + 1) : nullptr;

#pragma unroll
        for (int ks = 0; ks < 2; ks++) {
            uint4 a[4];
#pragma unroll
            for (int mf = 0; mf < 4; mf++)
                a[mf] = *reinterpret_cast<const uint4*>(
                    smc + abase + ks * 2048 + mf * 512 + lane * 16);
#pragma unroll
            for (int p = 0; p < 4; p++) {
                uint4 b = bfrag[ks * 4 + p];
#pragma unroll
                for (int mf = 0; mf < 4; mf++) {
                    mma_f16(acc[mf][2 * p],     a[mf].x, a[mf].y, a[mf].z, a[mf].w, b.x, b.y);
                    mma_f16(acc[mf][2 * p + 1], a[mf].x, a[mf].y, a[mf].z, a[mf].w, b.z, b.w);
                }
            }
            // refill this half's fragments for tile t+1 (registers now dead)
            if (bnext) {
#pragma unroll
                for (int p = 0; p < 4; p++)
                    bfrag[ks * 4 + p] = bnext[(ks * 16 + p) * 32];
            }
        }

        // L0 chunk epilogue: leaky -> fp16 -> APH fragment-major (conflict-free STS.128)
        if (t == 3 || t == 7) {
            if (t == 7) __syncthreads();   // all warps done reading aliased APX region
            int c = t >> 2;
#pragma unroll
            for (int mf = 0; mf < 4; mf++) {
#pragma unroll
                for (int p = 0; p < 4; p++) {
                    int K = c * 16 + wn * 4 + p;
                    int se = 2 * p, so = 2 * p + 1;
                    uint4 u = make_uint4(
                        pack_h2(leaky(acc[mf][se][0]), leaky(acc[mf][se][1])),
                        pack_h2(leaky(acc[mf][se][2]), leaky(acc[mf][se][3])),
                        pack_h2(leaky(acc[mf][so][0]), leaky(acc[mf][so][1])),
                        pack_h2(leaky(acc[mf][so][2]), leaky(acc[mf][so][3])));
                    *reinterpret_cast<uint4*>(
                        smc + APH_B + (K * 4 + mf) * 512 + lane * 16) = u;
                }
            }
            if (t == 7) __syncthreads();   // h1 complete before L1 A-reads
        }
        // L1 chunk epilogue: fused layer-2 dot (fp32)
        if (t == 23 || t == 39) {
            int c = (t - 8) >> 4;
#pragma unroll
            for (int mf = 0; mf < 4; mf++)
#pragma unroll
                for (int s = 0; s < 8; s++) {
                    int n = c * 256 + wn * 64 + 8 * s + 2 * t4;
                    float w2a = smf[W2_B / 4 + n], w2b = smf[W2_B / 4 + n + 1];
                    pr[mf * 2 + 0] += leaky(acc[mf][s][0]) * w2a + leaky(acc[mf][s][1]) * w2b;
                    pr[mf * 2 + 1] += leaky(acc[mf][s][2]) * w2a + leaky(acc[mf][s][3]) * w2b;
                }
        }
    }

#pragma unroll
    for (int j = 0; j < 8; j++) {
        pr[j] += __shfl_xor_sync(0xffffffffu, pr[j], 1);
        pr[j] += __shfl_xor_sync(0xffffffffu, pr[j], 2);
    }
    if (t4 == 0) {
#pragma unroll
        for (int mf = 0; mf < 4; mf++) {
            int R = mf * 16;
            atomicAdd(&smf[OUTS_B / 4 + R + g], pr[mf * 2 + 0]);
            atomicAdd(&smf[OUTS_B / 4 + R + g + 8], pr[mf * 2 + 1]);
        }
    }
    __syncthreads();
    if (tid < TM)
        out[(size_t)(n0 + tid) * DNODES + d] = smf[OUTS_B / 4 + tid];
}

extern "C" void kernel_launch(void* const* d_in, const int* in_sizes, int n_in,
                              void* d_out, int out_size) {
    (void)in_sizes; (void)n_in; (void)out_size;
    const float* x  = (const float*)d_in[0];
    const float* W0 = (const float*)d_in[1];
    const float* W1 = (const float*)d_in[2];
    const float* W2 = (const float*)d_in[3];
    float* out = (float*)d_out;

    __half* wp0; cudaGetSymbolAddress((void**)&wp0, g_Wp0);
    __half* wp1; cudaGetSymbolAddress((void**)&wp1, g_Wp1);

    {
        size_t t0 = (size_t)DNODES * 2 * 4 * 2 * 16 * 32;    // uint4 count L0
        size_t t1 = (size_t)DNODES * 2 * 16 * 2 * 16 * 32;   // uint4 count L1
        pack_w<DNODES, 2><<<(unsigned)((t0 + 255) / 256), 256>>>(W0, wp0);
        pack_w<HID, 4><<<(unsigned)((t1 + 255) / 256), 256>>>(W1, wp1);
    }

    cudaFuncSetAttribute(grandag_f16_kernel,
                         cudaFuncAttributeMaxDynamicSharedMemorySize, SMEMB);
    dim3 grid(NSAMP / TM, DNODES);   // x fastest: same-d blocks co-resident (L2/L1 weight reuse)
    grandag_f16_kernel<<<grid, THREADS, SMEMB>>>(x, W2, out);
}